// round 2
// baseline (speedup 1.0000x reference)
#include <cuda_runtime.h>

#define NN 50000
#define EE 800000
#define DIN 128
#define NH 4
#define CH 64
#define HC 256
#define NG 512
#define EPSBN 1e-5f
#define SLOPE 0.2f

// ---------------- scratch (device globals: no runtime allocation allowed) ----------------
__device__ float g_feat[(size_t)NN * HC];   // h = in @ W          (pre-attention features)
__device__ float g_res [(size_t)NN * HC];   // residual branch in @ resW + resb
__device__ float g_act [(size_t)NN * HC];   // layer output (gat+res, then BN+relu in place)
__device__ float g_es[NN * NH];
__device__ float g_ed[NN * NH];
__device__ int   g_rowptr[NN + 1];
__device__ int   g_cursor[NN];
__device__ int   g_srcsorted[EE];
__device__ int   g_blocksums[256];
__device__ int   g_blockoff[256];
__device__ float g_bnacc[2 * HC];
__device__ float g_bnA[HC];
__device__ float g_bnB[HC];
__device__ float g_pooled[NG * HC];

// ---------------- tiny utility kernels ----------------
__global__ void zero_float_kernel(float* p, int n) {
    int i = blockIdx.x * blockDim.x + threadIdx.x;
    if (i < n) p[i] = 0.0f;
}
__global__ void zero_int_kernel(int* p, int n) {
    int i = blockIdx.x * blockDim.x + threadIdx.x;
    if (i < n) p[i] = 0;
}
__global__ void copy_int_kernel(int* dst, const int* src, int n) {
    int i = blockIdx.x * blockDim.x + threadIdx.x;
    if (i < n) dst[i] = src[i];
}

// ---------------- CSR build ----------------
__global__ void count_deg_kernel(const int* __restrict__ ei) {
    int e = blockIdx.x * blockDim.x + threadIdx.x;
    if (e >= EE) return;
    atomicAdd(&g_cursor[ei[EE + e]], 1);   // dst
}

// exclusive scan over 256-chunks (Hillis-Steele in shared memory)
__global__ void scan_block_kernel(const int* __restrict__ in, int* __restrict__ out,
                                  int* __restrict__ blocksums, int n) {
    __shared__ int sh[256];
    int tid = threadIdx.x;
    int i = blockIdx.x * 256 + tid;
    int v = (i < n) ? in[i] : 0;
    sh[tid] = v;
    __syncthreads();
    for (int off = 1; off < 256; off <<= 1) {
        int t = (tid >= off) ? sh[tid - off] : 0;
        __syncthreads();
        sh[tid] += t;
        __syncthreads();
    }
    if (i < n) out[i] = sh[tid] - v;           // exclusive within block
    if (tid == 255 && blocksums) blocksums[blockIdx.x] = sh[255];
}

__global__ void scan_add_kernel(int* __restrict__ rowptr, const int* __restrict__ blockoff, int n) {
    int i = blockIdx.x * 256 + threadIdx.x;
    if (i < n) rowptr[i] += blockoff[blockIdx.x];
    if (blockIdx.x == 0 && threadIdx.x == 0) rowptr[n] = EE;
}

__global__ void fill_csr_kernel(const int* __restrict__ ei) {
    int e = blockIdx.x * blockDim.x + threadIdx.x;
    if (e >= EE) return;
    int s = ei[e];
    int d = ei[EE + e];
    int pos = atomicAdd(&g_cursor[d], 1);
    g_srcsorted[pos] = s;
}

// ---------------- dual GEMM: for z in {0,1}: C_z[Nr,M] = A[Nr,K] @ B_z[K,M] (+bias_z) -------
// 64x64 block tile, 16 k-tile, 256 threads, 4x4 microtile. blockIdx.z picks branch.
__global__ __launch_bounds__(256) void gemm2_kernel(
    const float* __restrict__ A,
    const float* __restrict__ B0, const float* __restrict__ B1,
    const float* __restrict__ bias1,
    float* __restrict__ C0, float* __restrict__ C1,
    int Nr, int K, int M)
{
    __shared__ float As[16][68];
    __shared__ float Bs[16][68];
    const float* B  = blockIdx.z ? B1 : B0;
    float*       Cc = blockIdx.z ? C1 : C0;
    const float* bias = blockIdx.z ? bias1 : nullptr;

    int tid = threadIdx.x;
    int tx = tid & 15;       // col group
    int ty = tid >> 4;       // row group
    int row0 = blockIdx.y * 64;
    int col0 = blockIdx.x * 64;

    float acc[4][4] = {};
    int ar = tid >> 2;             // 0..63
    int ak = (tid & 3) * 4;        // 0,4,8,12
    int bk = tid >> 4;             // 0..15
    int bm = (tid & 15) * 4;       // 0..60

    for (int k0 = 0; k0 < K; k0 += 16) {
        float4 av = make_float4(0.f, 0.f, 0.f, 0.f);
        int grow = row0 + ar;
        if (grow < Nr) av = *(const float4*)&A[(size_t)grow * K + k0 + ak];
        As[ak + 0][ar] = av.x; As[ak + 1][ar] = av.y;
        As[ak + 2][ar] = av.z; As[ak + 3][ar] = av.w;

        float4 bv = *(const float4*)&B[(size_t)(k0 + bk) * M + col0 + bm];
        *(float4*)&Bs[bk][bm] = bv;
        __syncthreads();

#pragma unroll
        for (int kk = 0; kk < 16; kk++) {
            float a4[4], b4[4];
#pragma unroll
            for (int i = 0; i < 4; i++) a4[i] = As[kk][ty * 4 + i];
#pragma unroll
            for (int j = 0; j < 4; j++) b4[j] = Bs[kk][tx * 4 + j];
#pragma unroll
            for (int i = 0; i < 4; i++)
#pragma unroll
                for (int j = 0; j < 4; j++)
                    acc[i][j] += a4[i] * b4[j];
        }
        __syncthreads();
    }
#pragma unroll
    for (int i = 0; i < 4; i++) {
        int r = row0 + ty * 4 + i;
        if (r < Nr) {
#pragma unroll
            for (int j = 0; j < 4; j++) {
                int c = col0 + tx * 4 + j;
                float v = acc[i][j];
                if (bias) v += bias[c];
                Cc[(size_t)r * M + c] = v;
            }
        }
    }
}

// ---------------- per-node attention dots: es/ed ----------------
__global__ __launch_bounds__(256) void dots_kernel(
    const float* __restrict__ feat, const float* __restrict__ asrc,
    const float* __restrict__ adst, float* __restrict__ es, float* __restrict__ ed)
{
    int gw = (blockIdx.x * blockDim.x + threadIdx.x) >> 5;
    int lane = threadIdx.x & 31;
    if (gw >= NN * NH) return;
    int node = gw >> 2, head = gw & 3;
    float2 f = *(const float2*)&feat[(size_t)node * HC + head * CH + 2 * lane];
    float2 a = *(const float2*)&asrc[head * CH + 2 * lane];
    float2 d = *(const float2*)&adst[head * CH + 2 * lane];
    float s = f.x * a.x + f.y * a.y;
    float t = f.x * d.x + f.y * d.y;
#pragma unroll
    for (int o = 16; o; o >>= 1) {
        s += __shfl_xor_sync(0xffffffffu, s, o);
        t += __shfl_xor_sync(0xffffffffu, t, o);
    }
    if (lane == 0) { es[node * NH + head] = s; ed[node * NH + head] = t; }
}

// ---------------- GAT softmax + aggregate: warp per (node, head) ----------------
__global__ __launch_bounds__(256) void agg_kernel(
    const float* __restrict__ feat, const float* __restrict__ es,
    const float* __restrict__ ed, const float* __restrict__ bias,
    const float* __restrict__ res, float* __restrict__ out)
{
    int gw = (blockIdx.x * blockDim.x + threadIdx.x) >> 5;
    int lane = threadIdx.x & 31;
    if (gw >= NN * NH) return;
    int node = gw >> 2, head = gw & 3;
    int s0 = g_rowptr[node], s1 = g_rowptr[node + 1];
    int ch = head * CH + 2 * lane;
    float accx = 0.f, accy = 0.f;

    if (s1 > s0) {
        float edv = ed[node * NH + head];
        // pass 1: max
        float m = -INFINITY;
        for (int k = s0 + lane; k < s1; k += 32) {
            int s = g_srcsorted[k];
            float e = es[s * NH + head] + edv;
            e = (e >= 0.f) ? e : SLOPE * e;
            m = fmaxf(m, e);
        }
#pragma unroll
        for (int o = 16; o; o >>= 1) m = fmaxf(m, __shfl_xor_sync(0xffffffffu, m, o));
        // pass 2: denominator
        float den = 0.f;
        for (int k = s0 + lane; k < s1; k += 32) {
            int s = g_srcsorted[k];
            float e = es[s * NH + head] + edv;
            e = (e >= 0.f) ? e : SLOPE * e;
            den += __expf(e - m);
        }
#pragma unroll
        for (int o = 16; o; o >>= 1) den += __shfl_xor_sync(0xffffffffu, den, o);
        float inv = 1.f / (den + 1e-16f);
        // pass 3: weighted gather (all lanes walk edges together; lanes = channels)
        for (int k = s0; k < s1; k++) {
            int s = g_srcsorted[k];
            float e = es[s * NH + head] + edv;
            e = (e >= 0.f) ? e : SLOPE * e;
            float w = __expf(e - m) * inv;
            float2 v = *(const float2*)&feat[(size_t)s * HC + ch];
            accx += w * v.x;
            accy += w * v.y;
        }
    }
    float2 bv = *(const float2*)&bias[ch];
    float2 rv = *(const float2*)&res[(size_t)node * HC + ch];
    float2 o2;
    o2.x = accx + bv.x + rv.x;
    o2.y = accy + bv.y + rv.y;
    *(float2*)&out[(size_t)node * HC + ch] = o2;
}

// ---------------- BatchNorm ----------------
__global__ __launch_bounds__(256) void bn_stats_kernel(const float* __restrict__ x) {
    int chn = threadIdx.x;
    int r0 = blockIdx.x * 64;
    int r1 = min(r0 + 64, NN);
    float s = 0.f, q = 0.f;
    for (int r = r0; r < r1; r++) {
        float v = x[(size_t)r * HC + chn];
        s += v; q += v * v;
    }
    atomicAdd(&g_bnacc[chn], s);
    atomicAdd(&g_bnacc[chn + HC], q);
}

__global__ void bn_finalize_kernel(const float* __restrict__ gma, const float* __restrict__ beta) {
    int c = threadIdx.x;
    float mean = g_bnacc[c] / (float)NN;
    float var  = g_bnacc[c + HC] / (float)NN - mean * mean;
    float a = gma[c] * rsqrtf(var + EPSBN);
    g_bnA[c] = a;
    g_bnB[c] = beta[c] - mean * a;
}

__global__ __launch_bounds__(256) void bn_apply_kernel(float* __restrict__ x) {
    int i = blockIdx.x * blockDim.x + threadIdx.x;
    if (i >= NN * HC / 4) return;
    float4 v = ((const float4*)x)[i];
    int c = (i * 4) & 255;
    v.x = fmaxf(v.x * g_bnA[c + 0] + g_bnB[c + 0], 0.f);
    v.y = fmaxf(v.y * g_bnA[c + 1] + g_bnB[c + 1], 0.f);
    v.z = fmaxf(v.z * g_bnA[c + 2] + g_bnB[c + 2], 0.f);
    v.w = fmaxf(v.w * g_bnA[c + 3] + g_bnB[c + 3], 0.f);
    ((float4*)x)[i] = v;
}

// ---------------- pooling (atomic-free; batch is sorted) ----------------
// One block per graph. Binary search node range, 256 threads = 256 channels.
__global__ __launch_bounds__(256) void pool_kernel(const float* __restrict__ act,
                                                   const int* __restrict__ batch) {
    __shared__ int s_lo, s_hi;
    int g = blockIdx.x;
    int t = threadIdx.x;
    if (t == 0) {
        // lower_bound(g)
        int lo = 0, hi = NN;
        while (lo < hi) { int mid = (lo + hi) >> 1; if (batch[mid] < g) lo = mid + 1; else hi = mid; }
        s_lo = lo;
        // lower_bound(g+1)
        int lo2 = lo; hi = NN;
        while (lo2 < hi) { int mid = (lo2 + hi) >> 1; if (batch[mid] < g + 1) lo2 = mid + 1; else hi = mid; }
        s_hi = lo2;
    }
    __syncthreads();
    int lo = s_lo, hi = s_hi;
    float s = 0.f;
    for (int r = lo; r < hi; r++) s += act[(size_t)r * HC + t];
    float inv = (hi > lo) ? 1.0f / (float)(hi - lo) : 0.0f;
    g_pooled[(size_t)g * HC + t] = s * inv;
}

// ---------------- graph-level MLP ----------------
__global__ __launch_bounds__(128) void mlp_kernel(
    const float* __restrict__ fc1W, const float* __restrict__ fc1b,
    const float* __restrict__ fc2W, const float* __restrict__ fc2b,
    float* __restrict__ out)
{
    __shared__ float row[HC];
    __shared__ float red[128];
    int g = blockIdx.x, t = threadIdx.x;
    row[t]       = g_pooled[(size_t)g * HC + t];
    row[t + 128] = g_pooled[(size_t)g * HC + t + 128];
    __syncthreads();
    float a = fc1b[t];
#pragma unroll 8
    for (int k = 0; k < HC; k++) a += row[k] * fc1W[k * 128 + t];
    a = fmaxf(a, 0.f);
    for (int j = 0; j < 2; j++) {
        red[t] = a * fc2W[t * 2 + j];
        __syncthreads();
        for (int off = 64; off; off >>= 1) {
            if (t < off) red[t] += red[t + off];
            __syncthreads();
        }
        if (t == 0) out[g * 2 + j] = red[0] + fc2b[j];
        __syncthreads();
    }
}

// ---------------- host side ----------------
static void* symp(const void* sym) {
    void* p = nullptr;
    cudaGetSymbolAddress(&p, sym);
    return p;
}

extern "C" void kernel_launch(void* const* d_in, const int* in_sizes, int n_in,
                              void* d_out, int out_size)
{
    const float* x        = (const float*)d_in[0];
    const int*   edge_idx = (const int*)  d_in[1];
    // d_in[2] edge_attr: unused by the reference
    const int*   batch    = (const int*)  d_in[3];
    const float* W1       = (const float*)d_in[4];
    const float* asrc1    = (const float*)d_in[5];
    const float* adst1    = (const float*)d_in[6];
    const float* b1       = (const float*)d_in[7];
    const float* res1W    = (const float*)d_in[8];
    const float* res1b    = (const float*)d_in[9];
    const float* bn1g     = (const float*)d_in[10];
    const float* bn1b     = (const float*)d_in[11];
    const float* W2       = (const float*)d_in[12];
    const float* asrc2    = (const float*)d_in[13];
    const float* adst2    = (const float*)d_in[14];
    const float* b2       = (const float*)d_in[15];
    const float* res2W    = (const float*)d_in[16];
    const float* res2b    = (const float*)d_in[17];
    const float* bn2g     = (const float*)d_in[18];
    const float* bn2b     = (const float*)d_in[19];
    const float* fc1W     = (const float*)d_in[20];
    const float* fc1b     = (const float*)d_in[21];
    const float* fc2W     = (const float*)d_in[22];
    const float* fc2b     = (const float*)d_in[23];
    float* out = (float*)d_out;

    float* feat  = (float*)symp(g_feat);
    float* res   = (float*)symp(g_res);
    float* act   = (float*)symp(g_act);
    float* es    = (float*)symp(g_es);
    float* ed    = (float*)symp(g_ed);
    int*   rowp  = (int*)  symp(g_rowptr);
    int*   curs  = (int*)  symp(g_cursor);
    int*   bsum  = (int*)  symp(g_blocksums);
    int*   boff  = (int*)  symp(g_blockoff);
    float* bnacc = (float*)symp(g_bnacc);

    const int NB = (NN + 255) / 256;      // 196
    const int EB = (EE + 255) / 256;      // 3125
    const int WARPBLKS = (NN * NH * 32 + 255) / 256;  // 25000
    dim3 gemm_grid(HC / 64, (NN + 63) / 64, 2);

    // ---- CSR build (reused by both layers) ----
    zero_int_kernel<<<NB, 256>>>(curs, NN);
    count_deg_kernel<<<EB, 256>>>(edge_idx);
    scan_block_kernel<<<NB, 256>>>(curs, rowp, bsum, NN);
    scan_block_kernel<<<1, 256>>>(bsum, boff, nullptr, NB);
    scan_add_kernel<<<NB, 256>>>(rowp, boff, NN);
    copy_int_kernel<<<NB, 256>>>(curs, rowp, NN);
    fill_csr_kernel<<<EB, 256>>>(edge_idx);

    // ---- layer 1 (input x, K=128) ----
    gemm2_kernel<<<gemm_grid, 256>>>(x, W1, res1W, res1b, feat, res, NN, DIN, HC);
    dots_kernel<<<WARPBLKS, 256>>>(feat, asrc1, adst1, es, ed);
    agg_kernel<<<WARPBLKS, 256>>>(feat, es, ed, b1, res, act);
    zero_float_kernel<<<2, 256>>>(bnacc, 2 * HC);
    bn_stats_kernel<<<(NN + 63) / 64, 256>>>(act);
    bn_finalize_kernel<<<1, HC>>>(bn1g, bn1b);
    bn_apply_kernel<<<(NN * HC / 4 + 255) / 256, 256>>>(act);

    // ---- layer 2 (input act, K=256) ----
    gemm2_kernel<<<gemm_grid, 256>>>(act, W2, res2W, res2b, feat, res, NN, HC, HC);
    dots_kernel<<<WARPBLKS, 256>>>(feat, asrc2, adst2, es, ed);
    agg_kernel<<<WARPBLKS, 256>>>(feat, es, ed, b2, res, act);
    zero_float_kernel<<<2, 256>>>(bnacc, 2 * HC);
    bn_stats_kernel<<<(NN + 63) / 64, 256>>>(act);
    bn_finalize_kernel<<<1, HC>>>(bn2g, bn2b);
    bn_apply_kernel<<<(NN * HC / 4 + 255) / 256, 256>>>(act);

    // ---- pooling + MLP ----
    pool_kernel<<<NG, 256>>>(act, batch);
    mlp_kernel<<<NG, 128>>>(fc1W, fc1b, fc2W, fc2b, out);
}

// round 3
// speedup vs baseline: 1.1969x; 1.1969x over previous
#include <cuda_runtime.h>
#include <cstdint>

#define NN 50000
#define EE 800000
#define DIN 128
#define NH 4
#define CH 64
#define HC 256
#define NG 512
#define EPSBN 1e-5f
#define SLOPE 0.2f

// ---------------- scratch (device globals: no runtime allocation allowed) ----------------
__device__ float g_feat[(size_t)NN * HC];   // h = in @ W          (pre-attention features)
__device__ float g_res [(size_t)NN * HC];   // residual branch in @ resW + resb
__device__ float g_act [(size_t)NN * HC];   // layer output (gat+res, then BN+relu in place)
__device__ float g_es[NN * NH];
__device__ float g_ed[NN * NH];
__device__ int   g_rowptr[NN + 1];
__device__ int   g_cursor[NN];
__device__ int   g_srcsorted[EE];
__device__ int   g_blocksums[256];
__device__ int   g_blockoff[256];
__device__ float g_bnacc[2 * HC];
__device__ float g_bnA[HC];
__device__ float g_bnB[HC];
__device__ float g_pooled[NG * HC];

// ---------------- tiny utility kernels ----------------
__global__ void zero_float_kernel(float* p, int n) {
    int i = blockIdx.x * blockDim.x + threadIdx.x;
    if (i < n) p[i] = 0.0f;
}
__global__ void zero_int_kernel(int* p, int n) {
    int i = blockIdx.x * blockDim.x + threadIdx.x;
    if (i < n) p[i] = 0;
}
__global__ void copy_int_kernel(int* dst, const int* src, int n) {
    int i = blockIdx.x * blockDim.x + threadIdx.x;
    if (i < n) dst[i] = src[i];
}

// ---------------- CSR build ----------------
__global__ void count_deg_kernel(const int* __restrict__ ei) {
    int e = blockIdx.x * blockDim.x + threadIdx.x;
    if (e >= EE) return;
    atomicAdd(&g_cursor[ei[EE + e]], 1);   // dst
}

__global__ void scan_block_kernel(const int* __restrict__ in, int* __restrict__ out,
                                  int* __restrict__ blocksums, int n) {
    __shared__ int sh[256];
    int tid = threadIdx.x;
    int i = blockIdx.x * 256 + tid;
    int v = (i < n) ? in[i] : 0;
    sh[tid] = v;
    __syncthreads();
    for (int off = 1; off < 256; off <<= 1) {
        int t = (tid >= off) ? sh[tid - off] : 0;
        __syncthreads();
        sh[tid] += t;
        __syncthreads();
    }
    if (i < n) out[i] = sh[tid] - v;           // exclusive within block
    if (tid == 255 && blocksums) blocksums[blockIdx.x] = sh[255];
}

__global__ void scan_add_kernel(int* __restrict__ rowptr, const int* __restrict__ blockoff, int n) {
    int i = blockIdx.x * 256 + threadIdx.x;
    if (i < n) rowptr[i] += blockoff[blockIdx.x];
    if (blockIdx.x == 0 && threadIdx.x == 0) rowptr[n] = EE;
}

__global__ void fill_csr_kernel(const int* __restrict__ ei) {
    int e = blockIdx.x * blockDim.x + threadIdx.x;
    if (e >= EE) return;
    int s = ei[e];
    int d = ei[EE + e];
    int pos = atomicAdd(&g_cursor[d], 1);
    g_srcsorted[pos] = s;
}

// ============================================================================
// Tensor-core dual GEMM (tf32 x3 error-compensated):
// for z in {0,1}:  C_z[Nr, 256] = A[Nr, K] @ B_z[K, 256] (+ bias_z)
// block tile 128x64, 8 warps (4 m x 2 n), warp tile 32x32, k-tile 16.
// Split a = a_hi + a_lo (hi = tf32 field); D = Ah*Bh + Ah*Bl + Al*Bh.
// ============================================================================
#define KT 16
#define AS_STRIDE 20   // 16 + 4 pad: frag loads hit all 32 banks exactly once
#define BS_STRIDE 72   // 64 + 8 pad: frag loads hit all 32 banks exactly once

__device__ __forceinline__ void mma_tf32(float* d, const uint32_t* a, const uint32_t* b) {
    asm volatile(
        "mma.sync.aligned.m16n8k8.row.col.f32.tf32.tf32.f32 "
        "{%0,%1,%2,%3}, {%4,%5,%6,%7}, {%8,%9}, {%0,%1,%2,%3};\n"
        : "+f"(d[0]), "+f"(d[1]), "+f"(d[2]), "+f"(d[3])
        : "r"(a[0]), "r"(a[1]), "r"(a[2]), "r"(a[3]), "r"(b[0]), "r"(b[1]));
}

__global__ __launch_bounds__(256) void gemm2tc_kernel(
    const float* __restrict__ A,
    const float* __restrict__ B0, const float* __restrict__ B1,
    const float* __restrict__ bias1,
    float* __restrict__ C0, float* __restrict__ C1,
    int Nr, int K)
{
    __shared__ uint32_t Ash[128 * AS_STRIDE];
    __shared__ uint32_t Asl[128 * AS_STRIDE];
    __shared__ uint32_t Bsh[KT * BS_STRIDE];
    __shared__ uint32_t Bsl[KT * BS_STRIDE];

    const float* B  = blockIdx.z ? B1 : B0;
    float*       Cc = blockIdx.z ? C1 : C0;
    const bool hasb = blockIdx.z != 0;

    const int tid  = threadIdx.x;
    const int lane = tid & 31;
    const int wid  = tid >> 5;
    const int warp_m = wid & 3;     // 0..3  -> 32-row slab
    const int warp_n = wid >> 2;    // 0..1  -> 32-col slab
    const int row0 = blockIdx.y * 128;
    const int col0 = blockIdx.x * 64;

    const int grp = lane >> 2;      // 0..7
    const int tig = lane & 3;       // 0..3

    float acc[2][4][4];
#pragma unroll
    for (int mt = 0; mt < 2; mt++)
#pragma unroll
        for (int nt = 0; nt < 4; nt++)
#pragma unroll
            for (int i = 0; i < 4; i++) acc[mt][nt][i] = 0.f;

    // global->smem mapping
    const int a_row = tid >> 2;           // float4 id f = tid and tid+256 -> rows tid>>2, (tid+256)>>2
    const int a_kq  = (tid & 3) * 4;
    const int b_row = tid >> 4;           // 0..15
    const int b_cq  = (tid & 15) * 4;

    for (int k0 = 0; k0 < K; k0 += KT) {
        // ---- load A tile (128 x 16), split hi/lo ----
#pragma unroll
        for (int h = 0; h < 2; h++) {
            int m = a_row + h * 64;
            int gr = row0 + m;
            float4 v = make_float4(0.f, 0.f, 0.f, 0.f);
            if (gr < Nr) v = *(const float4*)&A[(size_t)gr * K + k0 + a_kq];
            uint32_t hx = __float_as_uint(v.x) & 0xFFFFE000u;
            uint32_t hy = __float_as_uint(v.y) & 0xFFFFE000u;
            uint32_t hz = __float_as_uint(v.z) & 0xFFFFE000u;
            uint32_t hw = __float_as_uint(v.w) & 0xFFFFE000u;
            uint32_t* ph = &Ash[m * AS_STRIDE + a_kq];
            uint32_t* pl = &Asl[m * AS_STRIDE + a_kq];
            ph[0] = hx; ph[1] = hy; ph[2] = hz; ph[3] = hw;
            pl[0] = __float_as_uint(v.x - __uint_as_float(hx));
            pl[1] = __float_as_uint(v.y - __uint_as_float(hy));
            pl[2] = __float_as_uint(v.z - __uint_as_float(hz));
            pl[3] = __float_as_uint(v.w - __uint_as_float(hw));
        }
        // ---- load B tile (16 x 64), split hi/lo ----
        {
            float4 v = *(const float4*)&B[(size_t)(k0 + b_row) * HC + col0 + b_cq];
            uint32_t hx = __float_as_uint(v.x) & 0xFFFFE000u;
            uint32_t hy = __float_as_uint(v.y) & 0xFFFFE000u;
            uint32_t hz = __float_as_uint(v.z) & 0xFFFFE000u;
            uint32_t hw = __float_as_uint(v.w) & 0xFFFFE000u;
            uint32_t* ph = &Bsh[b_row * BS_STRIDE + b_cq];
            uint32_t* pl = &Bsl[b_row * BS_STRIDE + b_cq];
            ph[0] = hx; ph[1] = hy; ph[2] = hz; ph[3] = hw;
            pl[0] = __float_as_uint(v.x - __uint_as_float(hx));
            pl[1] = __float_as_uint(v.y - __uint_as_float(hy));
            pl[2] = __float_as_uint(v.z - __uint_as_float(hz));
            pl[3] = __float_as_uint(v.w - __uint_as_float(hw));
        }
        __syncthreads();

        // ---- 2 k8 steps ----
#pragma unroll
        for (int s = 0; s < 2; s++) {
            const int kc = s * 8;
            uint32_t ah[2][4], al[2][4], bh[4][2], bl[4][2];
#pragma unroll
            for (int mt = 0; mt < 2; mt++) {
                int r = warp_m * 32 + mt * 16 + grp;
                int base0 = r * AS_STRIDE + kc + tig;
                int base1 = (r + 8) * AS_STRIDE + kc + tig;
                ah[mt][0] = Ash[base0];     ah[mt][1] = Ash[base1];
                ah[mt][2] = Ash[base0 + 4]; ah[mt][3] = Ash[base1 + 4];
                al[mt][0] = Asl[base0];     al[mt][1] = Asl[base1];
                al[mt][2] = Asl[base0 + 4]; al[mt][3] = Asl[base1 + 4];
            }
#pragma unroll
            for (int nt = 0; nt < 4; nt++) {
                int n = warp_n * 32 + nt * 8 + grp;
                int base = (kc + tig) * BS_STRIDE + n;
                bh[nt][0] = Bsh[base];                  bh[nt][1] = Bsh[base + 4 * BS_STRIDE];
                bl[nt][0] = Bsl[base];                  bl[nt][1] = Bsl[base + 4 * BS_STRIDE];
            }
#pragma unroll
            for (int mt = 0; mt < 2; mt++)
#pragma unroll
                for (int nt = 0; nt < 4; nt++) {
                    mma_tf32(acc[mt][nt], al[mt], bh[nt]);  // Al*Bh
                    mma_tf32(acc[mt][nt], ah[mt], bl[nt]);  // Ah*Bl
                    mma_tf32(acc[mt][nt], ah[mt], bh[nt]);  // Ah*Bh (largest last)
                }
        }
        __syncthreads();
    }

    // ---- epilogue ----
#pragma unroll
    for (int mt = 0; mt < 2; mt++) {
        int r = row0 + warp_m * 32 + mt * 16 + grp;
#pragma unroll
        for (int nt = 0; nt < 4; nt++) {
            int c = col0 + warp_n * 32 + nt * 8 + 2 * tig;
            float bx = 0.f, by = 0.f;
            if (hasb) { bx = bias1[c]; by = bias1[c + 1]; }
            if (r < Nr) {
                float2 v0 = make_float2(acc[mt][nt][0] + bx, acc[mt][nt][1] + by);
                *(float2*)&Cc[(size_t)r * HC + c] = v0;
            }
            if (r + 8 < Nr) {
                float2 v1 = make_float2(acc[mt][nt][2] + bx, acc[mt][nt][3] + by);
                *(float2*)&Cc[(size_t)(r + 8) * HC + c] = v1;
            }
        }
    }
}

// ---------------- per-node attention dots: es/ed ----------------
__global__ __launch_bounds__(256) void dots_kernel(
    const float* __restrict__ feat, const float* __restrict__ asrc,
    const float* __restrict__ adst, float* __restrict__ es, float* __restrict__ ed)
{
    int gw = (blockIdx.x * blockDim.x + threadIdx.x) >> 5;
    int lane = threadIdx.x & 31;
    if (gw >= NN * NH) return;
    int node = gw >> 2, head = gw & 3;
    float2 f = *(const float2*)&feat[(size_t)node * HC + head * CH + 2 * lane];
    float2 a = *(const float2*)&asrc[head * CH + 2 * lane];
    float2 d = *(const float2*)&adst[head * CH + 2 * lane];
    float s = f.x * a.x + f.y * a.y;
    float t = f.x * d.x + f.y * d.y;
#pragma unroll
    for (int o = 16; o; o >>= 1) {
        s += __shfl_xor_sync(0xffffffffu, s, o);
        t += __shfl_xor_sync(0xffffffffu, t, o);
    }
    if (lane == 0) { es[node * NH + head] = s; ed[node * NH + head] = t; }
}

// ---------------- GAT softmax + aggregate: warp per (node, head) ----------------
__global__ __launch_bounds__(256) void agg_kernel(
    const float* __restrict__ feat, const float* __restrict__ es,
    const float* __restrict__ ed, const float* __restrict__ bias,
    const float* __restrict__ res, float* __restrict__ out)
{
    int gw = (blockIdx.x * blockDim.x + threadIdx.x) >> 5;
    int lane = threadIdx.x & 31;
    if (gw >= NN * NH) return;
    int node = gw >> 2, head = gw & 3;
    int s0 = g_rowptr[node], s1 = g_rowptr[node + 1];
    int ch = head * CH + 2 * lane;
    float accx = 0.f, accy = 0.f;

    if (s1 > s0) {
        float edv = ed[node * NH + head];
        float m = -INFINITY;
        for (int k = s0 + lane; k < s1; k += 32) {
            int s = g_srcsorted[k];
            float e = es[s * NH + head] + edv;
            e = (e >= 0.f) ? e : SLOPE * e;
            m = fmaxf(m, e);
        }
#pragma unroll
        for (int o = 16; o; o >>= 1) m = fmaxf(m, __shfl_xor_sync(0xffffffffu, m, o));
        float den = 0.f;
        for (int k = s0 + lane; k < s1; k += 32) {
            int s = g_srcsorted[k];
            float e = es[s * NH + head] + edv;
            e = (e >= 0.f) ? e : SLOPE * e;
            den += __expf(e - m);
        }
#pragma unroll
        for (int o = 16; o; o >>= 1) den += __shfl_xor_sync(0xffffffffu, den, o);
        float inv = 1.f / (den + 1e-16f);
        for (int k = s0; k < s1; k++) {
            int s = g_srcsorted[k];
            float e = es[s * NH + head] + edv;
            e = (e >= 0.f) ? e : SLOPE * e;
            float w = __expf(e - m) * inv;
            float2 v = *(const float2*)&feat[(size_t)s * HC + ch];
            accx += w * v.x;
            accy += w * v.y;
        }
    }
    float2 bv = *(const float2*)&bias[ch];
    float2 rv = *(const float2*)&res[(size_t)node * HC + ch];
    float2 o2;
    o2.x = accx + bv.x + rv.x;
    o2.y = accy + bv.y + rv.y;
    *(float2*)&out[(size_t)node * HC + ch] = o2;
}

// ---------------- BatchNorm ----------------
__global__ __launch_bounds__(256) void bn_stats_kernel(const float* __restrict__ x) {
    int chn = threadIdx.x;
    int r0 = blockIdx.x * 64;
    int r1 = min(r0 + 64, NN);
    float s = 0.f, q = 0.f;
    for (int r = r0; r < r1; r++) {
        float v = x[(size_t)r * HC + chn];
        s += v; q += v * v;
    }
    atomicAdd(&g_bnacc[chn], s);
    atomicAdd(&g_bnacc[chn + HC], q);
}

__global__ void bn_finalize_kernel(const float* __restrict__ gma, const float* __restrict__ beta) {
    int c = threadIdx.x;
    float mean = g_bnacc[c] / (float)NN;
    float var  = g_bnacc[c + HC] / (float)NN - mean * mean;
    float a = gma[c] * rsqrtf(var + EPSBN);
    g_bnA[c] = a;
    g_bnB[c] = beta[c] - mean * a;
}

__global__ __launch_bounds__(256) void bn_apply_kernel(float* __restrict__ x) {
    int i = blockIdx.x * blockDim.x + threadIdx.x;
    if (i >= NN * HC / 4) return;
    float4 v = ((const float4*)x)[i];
    int c = (i * 4) & 255;
    v.x = fmaxf(v.x * g_bnA[c + 0] + g_bnB[c + 0], 0.f);
    v.y = fmaxf(v.y * g_bnA[c + 1] + g_bnB[c + 1], 0.f);
    v.z = fmaxf(v.z * g_bnA[c + 2] + g_bnB[c + 2], 0.f);
    v.w = fmaxf(v.w * g_bnA[c + 3] + g_bnB[c + 3], 0.f);
    ((float4*)x)[i] = v;
}

// ---------------- pooling (atomic-free; batch is sorted) ----------------
__global__ __launch_bounds__(256) void pool_kernel(const float* __restrict__ act,
                                                   const int* __restrict__ batch) {
    __shared__ int s_lo, s_hi;
    int g = blockIdx.x;
    int t = threadIdx.x;
    if (t == 0) {
        int lo = 0, hi = NN;
        while (lo < hi) { int mid = (lo + hi) >> 1; if (batch[mid] < g) lo = mid + 1; else hi = mid; }
        s_lo = lo;
        int lo2 = lo; hi = NN;
        while (lo2 < hi) { int mid = (lo2 + hi) >> 1; if (batch[mid] < g + 1) lo2 = mid + 1; else hi = mid; }
        s_hi = lo2;
    }
    __syncthreads();
    int lo = s_lo, hi = s_hi;
    float s = 0.f;
    for (int r = lo; r < hi; r++) s += act[(size_t)r * HC + t];
    float inv = (hi > lo) ? 1.0f / (float)(hi - lo) : 0.0f;
    g_pooled[(size_t)g * HC + t] = s * inv;
}

// ---------------- graph-level MLP ----------------
__global__ __launch_bounds__(128) void mlp_kernel(
    const float* __restrict__ fc1W, const float* __restrict__ fc1b,
    const float* __restrict__ fc2W, const float* __restrict__ fc2b,
    float* __restrict__ out)
{
    __shared__ float row[HC];
    __shared__ float red[128];
    int g = blockIdx.x, t = threadIdx.x;
    row[t]       = g_pooled[(size_t)g * HC + t];
    row[t + 128] = g_pooled[(size_t)g * HC + t + 128];
    __syncthreads();
    float a = fc1b[t];
#pragma unroll 8
    for (int k = 0; k < HC; k++) a += row[k] * fc1W[k * 128 + t];
    a = fmaxf(a, 0.f);
    for (int j = 0; j < 2; j++) {
        red[t] = a * fc2W[t * 2 + j];
        __syncthreads();
        for (int off = 64; off; off >>= 1) {
            if (t < off) red[t] += red[t + off];
            __syncthreads();
        }
        if (t == 0) out[g * 2 + j] = red[0] + fc2b[j];
        __syncthreads();
    }
}

// ---------------- host side ----------------
static void* symp(const void* sym) {
    void* p = nullptr;
    cudaGetSymbolAddress(&p, sym);
    return p;
}

extern "C" void kernel_launch(void* const* d_in, const int* in_sizes, int n_in,
                              void* d_out, int out_size)
{
    const float* x        = (const float*)d_in[0];
    const int*   edge_idx = (const int*)  d_in[1];
    // d_in[2] edge_attr: unused by the reference
    const int*   batch    = (const int*)  d_in[3];
    const float* W1       = (const float*)d_in[4];
    const float* asrc1    = (const float*)d_in[5];
    const float* adst1    = (const float*)d_in[6];
    const float* b1       = (const float*)d_in[7];
    const float* res1W    = (const float*)d_in[8];
    const float* res1b    = (const float*)d_in[9];
    const float* bn1g     = (const float*)d_in[10];
    const float* bn1b     = (const float*)d_in[11];
    const float* W2       = (const float*)d_in[12];
    const float* asrc2    = (const float*)d_in[13];
    const float* adst2    = (const float*)d_in[14];
    const float* b2       = (const float*)d_in[15];
    const float* res2W    = (const float*)d_in[16];
    const float* res2b    = (const float*)d_in[17];
    const float* bn2g     = (const float*)d_in[18];
    const float* bn2b     = (const float*)d_in[19];
    const float* fc1W     = (const float*)d_in[20];
    const float* fc1b     = (const float*)d_in[21];
    const float* fc2W     = (const float*)d_in[22];
    const float* fc2b     = (const float*)d_in[23];
    float* out = (float*)d_out;

    float* feat  = (float*)symp(g_feat);
    float* res   = (float*)symp(g_res);
    float* act   = (float*)symp(g_act);
    float* es    = (float*)symp(g_es);
    float* ed    = (float*)symp(g_ed);
    int*   rowp  = (int*)  symp(g_rowptr);
    int*   curs  = (int*)  symp(g_cursor);
    int*   bsum  = (int*)  symp(g_blocksums);
    int*   boff  = (int*)  symp(g_blockoff);
    float* bnacc = (float*)symp(g_bnacc);

    const int NB = (NN + 255) / 256;      // 196
    const int EB = (EE + 255) / 256;      // 3125
    const int WARPBLKS = (NN * NH * 32 + 255) / 256;  // 25000
    dim3 gemm_grid(HC / 64, (NN + 127) / 128, 2);     // (4, 391, 2)

    // ---- CSR build part 1 (count + scan); fill happens after gemm so the
    //      heavy gemm2tc_kernel is launch #5 for the ncu capture window ----
    zero_int_kernel<<<NB, 256>>>(curs, NN);                 // 0
    count_deg_kernel<<<EB, 256>>>(edge_idx);                // 1
    scan_block_kernel<<<NB, 256>>>(curs, rowp, bsum, NN);   // 2
    scan_block_kernel<<<1, 256>>>(bsum, boff, nullptr, NB); // 3
    scan_add_kernel<<<NB, 256>>>(rowp, boff, NN);           // 4

    // ---- layer 1 GEMMs (input x, K=128) ----
    gemm2tc_kernel<<<gemm_grid, 256>>>(x, W1, res1W, res1b, feat, res, NN, DIN); // 5

    // ---- CSR build part 2 ----
    copy_int_kernel<<<NB, 256>>>(curs, rowp, NN);           // 6
    fill_csr_kernel<<<EB, 256>>>(edge_idx);                 // 7

    // ---- layer 1 rest ----
    dots_kernel<<<WARPBLKS, 256>>>(feat, asrc1, adst1, es, ed);
    agg_kernel<<<WARPBLKS, 256>>>(feat, es, ed, b1, res, act);
    zero_float_kernel<<<2, 256>>>(bnacc, 2 * HC);
    bn_stats_kernel<<<(NN + 63) / 64, 256>>>(act);
    bn_finalize_kernel<<<1, HC>>>(bn1g, bn1b);
    bn_apply_kernel<<<(NN * HC / 4 + 255) / 256, 256>>>(act);

    // ---- layer 2 (input act, K=256) ----
    gemm2tc_kernel<<<gemm_grid, 256>>>(act, W2, res2W, res2b, feat, res, NN, HC);
    dots_kernel<<<WARPBLKS, 256>>>(feat, asrc2, adst2, es, ed);
    agg_kernel<<<WARPBLKS, 256>>>(feat, es, ed, b2, res, act);
    zero_float_kernel<<<2, 256>>>(bnacc, 2 * HC);
    bn_stats_kernel<<<(NN + 63) / 64, 256>>>(act);
    bn_finalize_kernel<<<1, HC>>>(bn2g, bn2b);
    bn_apply_kernel<<<(NN * HC / 4 + 255) / 256, 256>>>(act);

    // ---- pooling + MLP ----
    pool_kernel<<<NG, 256>>>(act, batch);
    mlp_kernel<<<NG, 128>>>(fc1W, fc1b, fc2W, fc2b, out);
}

// round 4
// speedup vs baseline: 1.3629x; 1.1386x over previous
#include <cuda_runtime.h>
#include <cstdint>

#define NN 50000
#define EE 800000
#define DIN 128
#define NH 4
#define CH 64
#define HC 256
#define NG 512
#define EPSBN 1e-5f
#define SLOPE 0.2f

// ---------------- scratch ----------------
__device__ float g_feat[(size_t)NN * HC];
__device__ float g_res [(size_t)NN * HC];
__device__ float g_act [(size_t)NN * HC];
__device__ float g_es[NN * NH];
__device__ float g_ed[NN * NH];
__device__ int   g_rowptr[NN + 1];
__device__ int   g_cursor[NN];
__device__ int   g_srcsorted[EE];
__device__ int   g_blocksums[256];
__device__ int   g_blockoff[256];
__device__ float g_bnacc[2 * HC];
__device__ float g_bnA[HC];
__device__ float g_bnB[HC];
__device__ float g_pooled[NG * HC];

// ---------------- tiny utility kernels ----------------
__global__ void zero_float_kernel(float* p, int n) {
    int i = blockIdx.x * blockDim.x + threadIdx.x;
    if (i < n) p[i] = 0.0f;
}
__global__ void zero_int_kernel(int* p, int n) {
    int i = blockIdx.x * blockDim.x + threadIdx.x;
    if (i < n) p[i] = 0;
}
__global__ void copy_int_kernel(int* dst, const int* src, int n) {
    int i = blockIdx.x * blockDim.x + threadIdx.x;
    if (i < n) dst[i] = src[i];
}

// ---------------- CSR build ----------------
__global__ void count_deg_kernel(const int* __restrict__ ei) {
    int e = blockIdx.x * blockDim.x + threadIdx.x;
    if (e >= EE) return;
    atomicAdd(&g_cursor[ei[EE + e]], 1);   // dst
}

__global__ void scan_block_kernel(const int* __restrict__ in, int* __restrict__ out,
                                  int* __restrict__ blocksums, int n) {
    __shared__ int sh[256];
    int tid = threadIdx.x;
    int i = blockIdx.x * 256 + tid;
    int v = (i < n) ? in[i] : 0;
    sh[tid] = v;
    __syncthreads();
    for (int off = 1; off < 256; off <<= 1) {
        int t = (tid >= off) ? sh[tid - off] : 0;
        __syncthreads();
        sh[tid] += t;
        __syncthreads();
    }
    if (i < n) out[i] = sh[tid] - v;
    if (tid == 255 && blocksums) blocksums[blockIdx.x] = sh[255];
}

__global__ void scan_add_kernel(int* __restrict__ rowptr, const int* __restrict__ blockoff, int n) {
    int i = blockIdx.x * 256 + threadIdx.x;
    if (i < n) rowptr[i] += blockoff[blockIdx.x];
    if (blockIdx.x == 0 && threadIdx.x == 0) rowptr[n] = EE;
}

__global__ void fill_csr_kernel(const int* __restrict__ ei) {
    int e = blockIdx.x * blockDim.x + threadIdx.x;
    if (e >= EE) return;
    int s = ei[e];
    int d = ei[EE + e];
    int pos = atomicAdd(&g_cursor[d], 1);
    g_srcsorted[pos] = s;
}

// ============================================================================
// Tensor-core dual GEMM (tf32 x3), cp.async double-buffered, raw-fp32 smem
// with on-the-fly hi/lo split. Block tile 128x64 (col tile == one head),
// 8 warps (4m x 2n), warp tile 32x32, k-tile 16.
// z==0 branch additionally computes es/ed (attention dots) in the epilogue.
// ============================================================================
#define KT 16
#define AS_STRIDE 20   // 16 + 4 pad (floats); row pitch 80 B (16B-aligned)
#define BS_STRIDE 72   // 64 + 8 pad (floats); row pitch 288 B (16B-aligned)

__device__ __forceinline__ void mma_tf32(float* d, const uint32_t* a, const uint32_t* b) {
    asm volatile(
        "mma.sync.aligned.m16n8k8.row.col.f32.tf32.tf32.f32 "
        "{%0,%1,%2,%3}, {%4,%5,%6,%7}, {%8,%9}, {%0,%1,%2,%3};\n"
        : "+f"(d[0]), "+f"(d[1]), "+f"(d[2]), "+f"(d[3])
        : "r"(a[0]), "r"(a[1]), "r"(a[2]), "r"(a[3]), "r"(b[0]), "r"(b[1]));
}

__device__ __forceinline__ void cp_async16(float* smem_ptr, const float* gptr, bool pred) {
    uint32_t sa = (uint32_t)__cvta_generic_to_shared(smem_ptr);
    int bytes = pred ? 16 : 0;
    asm volatile("cp.async.ca.shared.global [%0], [%1], 16, %2;\n"
                 :: "r"(sa), "l"(gptr), "r"(bytes));
}

__device__ __forceinline__ void split_hl(uint32_t raw, uint32_t& h, uint32_t& l) {
    h = raw & 0xFFFFE000u;
    l = __float_as_uint(__uint_as_float(raw) - __uint_as_float(h));
}

__global__ __launch_bounds__(256) void gemm2tc_kernel(
    const float* __restrict__ A,
    const float* __restrict__ B0, const float* __restrict__ B1,
    const float* __restrict__ bias1,
    const float* __restrict__ asrc, const float* __restrict__ adst,
    float* __restrict__ C0, float* __restrict__ C1,
    float* __restrict__ es, float* __restrict__ ed,
    int Nr, int K)
{
    __shared__ float As[2][128 * AS_STRIDE];
    __shared__ float Bs[2][KT * BS_STRIDE];
    __shared__ float sEs[128], sEd[128];

    const float* B  = blockIdx.z ? B1 : B0;
    float*       Cc = blockIdx.z ? C1 : C0;
    const bool hasb = blockIdx.z != 0;

    const int tid  = threadIdx.x;
    const int lane = tid & 31;
    const int wid  = tid >> 5;
    const int warp_m = wid & 3;
    const int warp_n = wid >> 2;
    const int row0 = blockIdx.y * 128;
    const int col0 = blockIdx.x * 64;

    const int grp = lane >> 2;
    const int tig = lane & 3;

    if (tid < 128) { sEs[tid] = 0.f; sEd[tid] = 0.f; }

    float acc[2][4][4];
#pragma unroll
    for (int mt = 0; mt < 2; mt++)
#pragma unroll
        for (int nt = 0; nt < 4; nt++)
#pragma unroll
            for (int i = 0; i < 4; i++) acc[mt][nt][i] = 0.f;

    const int a_row = tid >> 2;           // 0..63
    const int a_kq  = (tid & 3) * 4;
    const int b_row = tid >> 4;           // 0..15
    const int b_cq  = (tid & 15) * 4;

    const int T = K / KT;

    // tile loader (async, one commit group per tile)
    auto load_tile = [&](int it, int buf) {
#pragma unroll
        for (int h = 0; h < 2; h++) {
            int m = a_row + h * 64;
            int gr = row0 + m;
            cp_async16(&As[buf][m * AS_STRIDE + a_kq],
                       &A[(size_t)gr * K + it * KT + a_kq], gr < Nr);
        }
        cp_async16(&Bs[buf][b_row * BS_STRIDE + b_cq],
                   &B[(size_t)(it * KT + b_row) * HC + col0 + b_cq], true);
        asm volatile("cp.async.commit_group;\n");
    };

    load_tile(0, 0);
    load_tile(1, 1);

    for (int it = 0; it < T; it++) {
        if (it < T - 1) asm volatile("cp.async.wait_group 1;\n");
        else            asm volatile("cp.async.wait_group 0;\n");
        __syncthreads();
        const float* as = As[it & 1];
        const float* bs = Bs[it & 1];

#pragma unroll
        for (int s = 0; s < 2; s++) {
            const int kc = s * 8;
            uint32_t ah[2][4], al[2][4], bh[4][2], bl[4][2];
#pragma unroll
            for (int mt = 0; mt < 2; mt++) {
                int base0 = (warp_m * 32 + mt * 16 + grp) * AS_STRIDE + kc + tig;
                int base1 = base0 + 8 * AS_STRIDE;
                split_hl(__float_as_uint(as[base0]),     ah[mt][0], al[mt][0]);
                split_hl(__float_as_uint(as[base1]),     ah[mt][1], al[mt][1]);
                split_hl(__float_as_uint(as[base0 + 4]), ah[mt][2], al[mt][2]);
                split_hl(__float_as_uint(as[base1 + 4]), ah[mt][3], al[mt][3]);
            }
#pragma unroll
            for (int nt = 0; nt < 4; nt++) {
                int n = warp_n * 32 + nt * 8 + grp;
                int base = (kc + tig) * BS_STRIDE + n;
                split_hl(__float_as_uint(bs[base]),                  bh[nt][0], bl[nt][0]);
                split_hl(__float_as_uint(bs[base + 4 * BS_STRIDE]),  bh[nt][1], bl[nt][1]);
            }
#pragma unroll
            for (int mt = 0; mt < 2; mt++)
#pragma unroll
                for (int nt = 0; nt < 4; nt++) {
                    mma_tf32(acc[mt][nt], al[mt], bh[nt]);
                    mma_tf32(acc[mt][nt], ah[mt], bl[nt]);
                    mma_tf32(acc[mt][nt], ah[mt], bh[nt]);
                }
        }
        __syncthreads();
        if (it + 2 < T) load_tile(it + 2, it & 1);
    }

    // ---- C write ----
#pragma unroll
    for (int mt = 0; mt < 2; mt++) {
        int r = row0 + warp_m * 32 + mt * 16 + grp;
#pragma unroll
        for (int nt = 0; nt < 4; nt++) {
            int c = col0 + warp_n * 32 + nt * 8 + 2 * tig;
            float bx = 0.f, by = 0.f;
            if (hasb) { bx = bias1[c]; by = bias1[c + 1]; }
            if (r < Nr)
                *(float2*)&Cc[(size_t)r * HC + c] =
                    make_float2(acc[mt][nt][0] + bx, acc[mt][nt][1] + by);
            if (r + 8 < Nr)
                *(float2*)&Cc[(size_t)(r + 8) * HC + c] =
                    make_float2(acc[mt][nt][2] + bx, acc[mt][nt][3] + by);
        }
    }

    // ---- fused attention dots (feat branch only): col tile == head blockIdx.x ----
    if (blockIdx.z == 0) {
        const int head = blockIdx.x;
        float pes[2][2] = {{0.f, 0.f}, {0.f, 0.f}};
        float ped[2][2] = {{0.f, 0.f}, {0.f, 0.f}};
#pragma unroll
        for (int mt = 0; mt < 2; mt++)
#pragma unroll
            for (int nt = 0; nt < 4; nt++) {
                int cl = warp_n * 32 + nt * 8 + 2 * tig;
                float a0 = asrc[head * CH + cl], a1 = asrc[head * CH + cl + 1];
                float d0 = adst[head * CH + cl], d1 = adst[head * CH + cl + 1];
                pes[mt][0] += acc[mt][nt][0] * a0 + acc[mt][nt][1] * a1;
                pes[mt][1] += acc[mt][nt][2] * a0 + acc[mt][nt][3] * a1;
                ped[mt][0] += acc[mt][nt][0] * d0 + acc[mt][nt][1] * d1;
                ped[mt][1] += acc[mt][nt][2] * d0 + acc[mt][nt][3] * d1;
            }
        // reduce across tig (lanes grp*4 + {0..3})
#pragma unroll
        for (int o = 1; o <= 2; o <<= 1) {
#pragma unroll
            for (int mt = 0; mt < 2; mt++)
#pragma unroll
                for (int hh = 0; hh < 2; hh++) {
                    pes[mt][hh] += __shfl_xor_sync(0xffffffffu, pes[mt][hh], o);
                    ped[mt][hh] += __shfl_xor_sync(0xffffffffu, ped[mt][hh], o);
                }
        }
        if (tig == 0) {
#pragma unroll
            for (int mt = 0; mt < 2; mt++)
#pragma unroll
                for (int hh = 0; hh < 2; hh++) {
                    int lr = warp_m * 32 + mt * 16 + hh * 8 + grp;
                    atomicAdd(&sEs[lr], pes[mt][hh]);
                    atomicAdd(&sEd[lr], ped[mt][hh]);
                }
        }
        __syncthreads();
        if (tid < 128) {
            int node = row0 + tid;
            if (node < Nr) {
                es[node * NH + head] = sEs[tid];
                ed[node * NH + head] = sEd[tid];
            }
        }
    }
}

// ---------------- GAT softmax + aggregate: warp per (node, head) ----------------
__global__ __launch_bounds__(256) void agg_kernel(
    const float* __restrict__ feat, const float* __restrict__ es,
    const float* __restrict__ ed, const float* __restrict__ bias,
    const float* __restrict__ res, float* __restrict__ out)
{
    int gw = (blockIdx.x * blockDim.x + threadIdx.x) >> 5;
    int lane = threadIdx.x & 31;
    if (gw >= NN * NH) return;
    int node = gw >> 2, head = gw & 3;
    int s0 = g_rowptr[node], s1 = g_rowptr[node + 1];
    int ch = head * CH + 2 * lane;
    float accx = 0.f, accy = 0.f;

    if (s1 > s0) {
        float edv = ed[node * NH + head];
        float m = -INFINITY;
        for (int k = s0 + lane; k < s1; k += 32) {
            int s = g_srcsorted[k];
            float e = es[s * NH + head] + edv;
            e = (e >= 0.f) ? e : SLOPE * e;
            m = fmaxf(m, e);
        }
#pragma unroll
        for (int o = 16; o; o >>= 1) m = fmaxf(m, __shfl_xor_sync(0xffffffffu, m, o));
        float den = 0.f;
        for (int k = s0 + lane; k < s1; k += 32) {
            int s = g_srcsorted[k];
            float e = es[s * NH + head] + edv;
            e = (e >= 0.f) ? e : SLOPE * e;
            den += __expf(e - m);
        }
#pragma unroll
        for (int o = 16; o; o >>= 1) den += __shfl_xor_sync(0xffffffffu, den, o);
        float inv = 1.f / (den + 1e-16f);
        for (int k = s0; k < s1; k++) {
            int s = g_srcsorted[k];
            float e = es[s * NH + head] + edv;
            e = (e >= 0.f) ? e : SLOPE * e;
            float w = __expf(e - m) * inv;
            float2 v = *(const float2*)&feat[(size_t)s * HC + ch];
            accx += w * v.x;
            accy += w * v.y;
        }
    }
    float2 bv = *(const float2*)&bias[ch];
    float2 rv = *(const float2*)&res[(size_t)node * HC + ch];
    float2 o2;
    o2.x = accx + bv.x + rv.x;
    o2.y = accy + bv.y + rv.y;
    *(float2*)&out[(size_t)node * HC + ch] = o2;
}

// ---------------- BatchNorm ----------------
__global__ __launch_bounds__(256) void bn_stats_kernel(const float* __restrict__ x) {
    int chn = threadIdx.x;
    int r0 = blockIdx.x * 64;
    int r1 = min(r0 + 64, NN);
    float s = 0.f, q = 0.f;
    for (int r = r0; r < r1; r++) {
        float v = x[(size_t)r * HC + chn];
        s += v; q += v * v;
    }
    atomicAdd(&g_bnacc[chn], s);
    atomicAdd(&g_bnacc[chn + HC], q);
}

__global__ void bn_finalize_kernel(const float* __restrict__ gma, const float* __restrict__ beta) {
    int c = threadIdx.x;
    float mean = g_bnacc[c] / (float)NN;
    float var  = g_bnacc[c + HC] / (float)NN - mean * mean;
    float a = gma[c] * rsqrtf(var + EPSBN);
    g_bnA[c] = a;
    g_bnB[c] = beta[c] - mean * a;
}

__global__ __launch_bounds__(256) void bn_apply_kernel(float* __restrict__ x) {
    int i = blockIdx.x * blockDim.x + threadIdx.x;
    if (i >= NN * HC / 4) return;
    float4 v = ((const float4*)x)[i];
    int c = (i * 4) & 255;
    v.x = fmaxf(v.x * g_bnA[c + 0] + g_bnB[c + 0], 0.f);
    v.y = fmaxf(v.y * g_bnA[c + 1] + g_bnB[c + 1], 0.f);
    v.z = fmaxf(v.z * g_bnA[c + 2] + g_bnB[c + 2], 0.f);
    v.w = fmaxf(v.w * g_bnA[c + 3] + g_bnB[c + 3], 0.f);
    ((float4*)x)[i] = v;
}

// ---------------- pooling (atomic-free; batch is sorted) ----------------
__global__ __launch_bounds__(256) void pool_kernel(const float* __restrict__ act,
                                                   const int* __restrict__ batch) {
    __shared__ int s_lo, s_hi;
    int g = blockIdx.x;
    int t = threadIdx.x;
    if (t == 0) {
        int lo = 0, hi = NN;
        while (lo < hi) { int mid = (lo + hi) >> 1; if (batch[mid] < g) lo = mid + 1; else hi = mid; }
        s_lo = lo;
        int lo2 = lo; hi = NN;
        while (lo2 < hi) { int mid = (lo2 + hi) >> 1; if (batch[mid] < g + 1) lo2 = mid + 1; else hi = mid; }
        s_hi = lo2;
    }
    __syncthreads();
    int lo = s_lo, hi = s_hi;
    float s = 0.f;
    for (int r = lo; r < hi; r++) s += act[(size_t)r * HC + t];
    float inv = (hi > lo) ? 1.0f / (float)(hi - lo) : 0.0f;
    g_pooled[(size_t)g * HC + t] = s * inv;
}

// ---------------- graph-level MLP ----------------
__global__ __launch_bounds__(128) void mlp_kernel(
    const float* __restrict__ fc1W, const float* __restrict__ fc1b,
    const float* __restrict__ fc2W, const float* __restrict__ fc2b,
    float* __restrict__ out)
{
    __shared__ float row[HC];
    __shared__ float red[128];
    int g = blockIdx.x, t = threadIdx.x;
    row[t]       = g_pooled[(size_t)g * HC + t];
    row[t + 128] = g_pooled[(size_t)g * HC + t + 128];
    __syncthreads();
    float a = fc1b[t];
#pragma unroll 8
    for (int k = 0; k < HC; k++) a += row[k] * fc1W[k * 128 + t];
    a = fmaxf(a, 0.f);
    for (int j = 0; j < 2; j++) {
        red[t] = a * fc2W[t * 2 + j];
        __syncthreads();
        for (int off = 64; off; off >>= 1) {
            if (t < off) red[t] += red[t + off];
            __syncthreads();
        }
        if (t == 0) out[g * 2 + j] = red[0] + fc2b[j];
        __syncthreads();
    }
}

// ---------------- host side ----------------
static void* symp(const void* sym) {
    void* p = nullptr;
    cudaGetSymbolAddress(&p, sym);
    return p;
}

extern "C" void kernel_launch(void* const* d_in, const int* in_sizes, int n_in,
                              void* d_out, int out_size)
{
    const float* x        = (const float*)d_in[0];
    const int*   edge_idx = (const int*)  d_in[1];
    const int*   batch    = (const int*)  d_in[3];
    const float* W1       = (const float*)d_in[4];
    const float* asrc1    = (const float*)d_in[5];
    const float* adst1    = (const float*)d_in[6];
    const float* b1       = (const float*)d_in[7];
    const float* res1W    = (const float*)d_in[8];
    const float* res1b    = (const float*)d_in[9];
    const float* bn1g     = (const float*)d_in[10];
    const float* bn1b     = (const float*)d_in[11];
    const float* W2       = (const float*)d_in[12];
    const float* asrc2    = (const float*)d_in[13];
    const float* adst2    = (const float*)d_in[14];
    const float* b2       = (const float*)d_in[15];
    const float* res2W    = (const float*)d_in[16];
    const float* res2b    = (const float*)d_in[17];
    const float* bn2g     = (const float*)d_in[18];
    const float* bn2b     = (const float*)d_in[19];
    const float* fc1W     = (const float*)d_in[20];
    const float* fc1b     = (const float*)d_in[21];
    const float* fc2W     = (const float*)d_in[22];
    const float* fc2b     = (const float*)d_in[23];
    float* out = (float*)d_out;

    float* feat  = (float*)symp(g_feat);
    float* res   = (float*)symp(g_res);
    float* act   = (float*)symp(g_act);
    float* es    = (float*)symp(g_es);
    float* ed    = (float*)symp(g_ed);
    int*   rowp  = (int*)  symp(g_rowptr);
    int*   curs  = (int*)  symp(g_cursor);
    int*   bsum  = (int*)  symp(g_blocksums);
    int*   boff  = (int*)  symp(g_blockoff);
    float* bnacc = (float*)symp(g_bnacc);

    const int NB = (NN + 255) / 256;
    const int EB = (EE + 255) / 256;
    const int WARPBLKS = (NN * NH * 32 + 255) / 256;
    dim3 gemm_grid(HC / 64, (NN + 127) / 128, 2);

    // ---- CSR build ----
    zero_int_kernel<<<NB, 256>>>(curs, NN);
    count_deg_kernel<<<EB, 256>>>(edge_idx);
    scan_block_kernel<<<NB, 256>>>(curs, rowp, bsum, NN);
    scan_block_kernel<<<1, 256>>>(bsum, boff, nullptr, NB);
    scan_add_kernel<<<NB, 256>>>(rowp, boff, NN);

    // ---- layer 1 (input x, K=128): GEMM + fused dots ----
    gemm2tc_kernel<<<gemm_grid, 256>>>(x, W1, res1W, res1b, asrc1, adst1,
                                       feat, res, es, ed, NN, DIN);

    copy_int_kernel<<<NB, 256>>>(curs, rowp, NN);
    fill_csr_kernel<<<EB, 256>>>(edge_idx);

    agg_kernel<<<WARPBLKS, 256>>>(feat, es, ed, b1, res, act);
    zero_float_kernel<<<2, 256>>>(bnacc, 2 * HC);
    bn_stats_kernel<<<(NN + 63) / 64, 256>>>(act);
    bn_finalize_kernel<<<1, HC>>>(bn1g, bn1b);
    bn_apply_kernel<<<(NN * HC / 4 + 255) / 256, 256>>>(act);

    // ---- layer 2 (input act, K=256) ----
    gemm2tc_kernel<<<gemm_grid, 256>>>(act, W2, res2W, res2b, asrc2, adst2,
                                       feat, res, es, ed, NN, HC);
    agg_kernel<<<WARPBLKS, 256>>>(feat, es, ed, b2, res, act);
    zero_float_kernel<<<2, 256>>>(bnacc, 2 * HC);
    bn_stats_kernel<<<(NN + 63) / 64, 256>>>(act);
    bn_finalize_kernel<<<1, HC>>>(bn2g, bn2b);
    bn_apply_kernel<<<(NN * HC / 4 + 255) / 256, 256>>>(act);

    // ---- pooling + MLP ----
    pool_kernel<<<NG, 256>>>(act, batch);
    mlp_kernel<<<NG, 128>>>(fc1W, fc1b, fc2W, fc2b, out);
}

// round 5
// speedup vs baseline: 1.4574x; 1.0694x over previous
#include <cuda_runtime.h>
#include <cstdint>

#define NN 50000
#define EE 800000
#define DIN 128
#define NH 4
#define CH 64
#define HC 256
#define NG 512
#define EPSBN 1e-5f
#define SLOPE 0.2f

// ---------------- scratch ----------------
__device__ float g_feat[(size_t)NN * HC];
__device__ float g_res [(size_t)NN * HC];
__device__ float g_act [(size_t)NN * HC];
__device__ float g_es[NN * NH];
__device__ float g_ed[NN * NH];
__device__ int   g_rowptr[NN + 1];
__device__ int   g_cursor[NN];
__device__ int   g_srcsorted[EE];
__device__ int   g_blocksums[256];
__device__ int   g_blockoff[256];
__device__ float g_bnacc[2 * HC];
__device__ float g_bnA[HC];
__device__ float g_bnB[HC];
__device__ float g_pooled[NG * HC];

// ---------------- tiny utility kernels ----------------
__global__ void zero_float_kernel(float* p, int n) {
    int i = blockIdx.x * blockDim.x + threadIdx.x;
    if (i < n) p[i] = 0.0f;
}
__global__ void zero_int_kernel(int* p, int n) {
    int i = blockIdx.x * blockDim.x + threadIdx.x;
    if (i < n) p[i] = 0;
}
__global__ void copy_int_kernel(int* dst, const int* src, int n) {
    int i = blockIdx.x * blockDim.x + threadIdx.x;
    if (i < n) dst[i] = src[i];
}

// ---------------- CSR build ----------------
__global__ void count_deg_kernel(const int* __restrict__ ei) {
    int e = blockIdx.x * blockDim.x + threadIdx.x;
    if (e >= EE) return;
    atomicAdd(&g_cursor[ei[EE + e]], 1);   // dst
}

__global__ void scan_block_kernel(const int* __restrict__ in, int* __restrict__ out,
                                  int* __restrict__ blocksums, int n) {
    __shared__ int sh[256];
    int tid = threadIdx.x;
    int i = blockIdx.x * 256 + tid;
    int v = (i < n) ? in[i] : 0;
    sh[tid] = v;
    __syncthreads();
    for (int off = 1; off < 256; off <<= 1) {
        int t = (tid >= off) ? sh[tid - off] : 0;
        __syncthreads();
        sh[tid] += t;
        __syncthreads();
    }
    if (i < n) out[i] = sh[tid] - v;
    if (tid == 255 && blocksums) blocksums[blockIdx.x] = sh[255];
}

__global__ void scan_add_kernel(int* __restrict__ rowptr, const int* __restrict__ blockoff, int n) {
    int i = blockIdx.x * 256 + threadIdx.x;
    if (i < n) rowptr[i] += blockoff[blockIdx.x];
    if (blockIdx.x == 0 && threadIdx.x == 0) rowptr[n] = EE;
}

__global__ void fill_csr_kernel(const int* __restrict__ ei) {
    int e = blockIdx.x * blockDim.x + threadIdx.x;
    if (e >= EE) return;
    int s = ei[e];
    int d = ei[EE + e];
    int pos = atomicAdd(&g_cursor[d], 1);
    g_srcsorted[pos] = s;
}

// ============================================================================
// Tensor-core dual GEMM (bf16 x3 error-compensated), cp.async double-buffered.
// for z in {0,1}:  C_z[Nr, 256] = f(A)[Nr, K] @ B_z[K, 256] (+ bias_z)
// where f = identity, or fused BN+ReLU (x*bnA[k]+bnB[k], clamped) when bnA!=0.
// Block tile 128x64 (col tile == one head), 8 warps (4m x 2n), warp 32x32,
// k-tile 16, mma.m16n8k16.bf16 with hi/lo split (3 products).
// z==0 branch computes es/ed (attention dots) in the epilogue.
// ============================================================================
#define KT 16
#define AS_STRIDE 24   // 16 + 8 pad: conflict-free LDS.64 fragment loads
#define BS_STRIDE 68   // 64 + 4 pad: conflict-free LDS.32 fragment loads

__device__ __forceinline__ void mma_bf16(float* d, const uint32_t* a,
                                         uint32_t b0, uint32_t b1) {
    asm volatile(
        "mma.sync.aligned.m16n8k16.row.col.f32.bf16.bf16.f32 "
        "{%0,%1,%2,%3}, {%4,%5,%6,%7}, {%8,%9}, {%0,%1,%2,%3};\n"
        : "+f"(d[0]), "+f"(d[1]), "+f"(d[2]), "+f"(d[3])
        : "r"(a[0]), "r"(a[1]), "r"(a[2]), "r"(a[3]), "r"(b0), "r"(b1));
}

__device__ __forceinline__ void cp_async16(float* smem_ptr, const float* gptr, bool pred) {
    uint32_t sa = (uint32_t)__cvta_generic_to_shared(smem_ptr);
    int bytes = pred ? 16 : 0;
    asm volatile("cp.async.ca.shared.global [%0], [%1], 16, %2;\n"
                 :: "r"(sa), "l"(gptr), "r"(bytes));
}

// float2 -> (hi bf16x2, lo bf16x2) split; lo = residual after bf16 rounding.
__device__ __forceinline__ void f2_split(float2 v, uint32_t& h, uint32_t& l) {
    asm("cvt.rn.bf16x2.f32 %0, %1, %2;" : "=r"(h) : "f"(v.y), "f"(v.x));
    float hx = __uint_as_float(h << 16);
    float hy = __uint_as_float(h & 0xFFFF0000u);
    asm("cvt.rn.bf16x2.f32 %0, %1, %2;" : "=r"(l) : "f"(v.y - hy), "f"(v.x - hx));
}

__global__ __launch_bounds__(256) void gemm2tc_kernel(
    const float* __restrict__ A,
    const float* __restrict__ B0, const float* __restrict__ B1,
    const float* __restrict__ bias1,
    const float* __restrict__ asrc, const float* __restrict__ adst,
    const float* __restrict__ bnAp, const float* __restrict__ bnBp,
    float* __restrict__ C0, float* __restrict__ C1,
    float* __restrict__ es, float* __restrict__ ed,
    int Nr, int K)
{
    __shared__ float As[2][128 * AS_STRIDE];
    __shared__ float Bs[2][KT * BS_STRIDE];
    __shared__ float sEs[128], sEd[128];
    __shared__ float sBnA[HC], sBnB[HC];

    const float* B  = blockIdx.z ? B1 : B0;
    float*       Cc = blockIdx.z ? C1 : C0;
    const bool hasb = blockIdx.z != 0;
    const bool useBn = (bnAp != nullptr);

    const int tid  = threadIdx.x;
    const int lane = tid & 31;
    const int wid  = tid >> 5;
    const int warp_m = wid & 3;
    const int warp_n = wid >> 2;
    const int row0 = blockIdx.y * 128;
    const int col0 = blockIdx.x * 64;

    const int grp = lane >> 2;
    const int tig = lane & 3;

    if (tid < 128) { sEs[tid] = 0.f; sEd[tid] = 0.f; }
    if (useBn) { sBnA[tid] = bnAp[tid]; sBnB[tid] = bnBp[tid]; }

    float acc[2][4][4];
#pragma unroll
    for (int mt = 0; mt < 2; mt++)
#pragma unroll
        for (int nt = 0; nt < 4; nt++)
#pragma unroll
            for (int i = 0; i < 4; i++) acc[mt][nt][i] = 0.f;

    const int a_row = tid >> 2;           // 0..63
    const int a_kq  = (tid & 3) * 4;
    const int b_row = tid >> 4;           // 0..15
    const int b_cq  = (tid & 15) * 4;

    const int T = K / KT;

    auto load_tile = [&](int it, int buf) {
#pragma unroll
        for (int h = 0; h < 2; h++) {
            int m = a_row + h * 64;
            int gr = row0 + m;
            cp_async16(&As[buf][m * AS_STRIDE + a_kq],
                       &A[(size_t)gr * K + it * KT + a_kq], gr < Nr);
        }
        cp_async16(&Bs[buf][b_row * BS_STRIDE + b_cq],
                   &B[(size_t)(it * KT + b_row) * HC + col0 + b_cq], true);
        asm volatile("cp.async.commit_group;\n");
    };

    load_tile(0, 0);
    load_tile(1, 1);

    for (int it = 0; it < T; it++) {
        if (it < T - 1) asm volatile("cp.async.wait_group 1;\n");
        else            asm volatile("cp.async.wait_group 0;\n");
        __syncthreads();
        const float* as = As[it & 1];
        const float* bs = Bs[it & 1];

        // BN coefficients for this tile's k-range (uniform per thread's k cols)
        float2 bnA0, bnB0, bnA1, bnB1;
        if (useBn) {
            int kk = it * KT + 2 * tig;
            bnA0 = *(const float2*)&sBnA[kk];     bnB0 = *(const float2*)&sBnB[kk];
            bnA1 = *(const float2*)&sBnA[kk + 8]; bnB1 = *(const float2*)&sBnB[kk + 8];
        }

        // ---- A fragments ----
        uint32_t ah[2][4], al[2][4];
#pragma unroll
        for (int mt = 0; mt < 2; mt++) {
            int rbase = (warp_m * 32 + mt * 16 + grp) * AS_STRIDE;
            float2 v00 = *(const float2*)&as[rbase + 2 * tig];
            float2 v10 = *(const float2*)&as[rbase + 8 * AS_STRIDE + 2 * tig];
            float2 v01 = *(const float2*)&as[rbase + 2 * tig + 8];
            float2 v11 = *(const float2*)&as[rbase + 8 * AS_STRIDE + 2 * tig + 8];
            if (useBn) {
                v00.x = fmaxf(v00.x * bnA0.x + bnB0.x, 0.f);
                v00.y = fmaxf(v00.y * bnA0.y + bnB0.y, 0.f);
                v10.x = fmaxf(v10.x * bnA0.x + bnB0.x, 0.f);
                v10.y = fmaxf(v10.y * bnA0.y + bnB0.y, 0.f);
                v01.x = fmaxf(v01.x * bnA1.x + bnB1.x, 0.f);
                v01.y = fmaxf(v01.y * bnA1.y + bnB1.y, 0.f);
                v11.x = fmaxf(v11.x * bnA1.x + bnB1.x, 0.f);
                v11.y = fmaxf(v11.y * bnA1.y + bnB1.y, 0.f);
            }
            f2_split(v00, ah[mt][0], al[mt][0]);
            f2_split(v10, ah[mt][1], al[mt][1]);
            f2_split(v01, ah[mt][2], al[mt][2]);
            f2_split(v11, ah[mt][3], al[mt][3]);
        }

        // ---- B fragments + MMAs ----
#pragma unroll
        for (int nt = 0; nt < 4; nt++) {
            int n = warp_n * 32 + nt * 8 + grp;
            float2 w0 = make_float2(bs[(2 * tig) * BS_STRIDE + n],
                                    bs[(2 * tig + 1) * BS_STRIDE + n]);
            float2 w1 = make_float2(bs[(2 * tig + 8) * BS_STRIDE + n],
                                    bs[(2 * tig + 9) * BS_STRIDE + n]);
            uint32_t bh0, bl0, bh1, bl1;
            f2_split(w0, bh0, bl0);
            f2_split(w1, bh1, bl1);
#pragma unroll
            for (int mt = 0; mt < 2; mt++) {
                mma_bf16(acc[mt][nt], al[mt], bh0, bh1);  // Al*Bh
                mma_bf16(acc[mt][nt], ah[mt], bl0, bl1);  // Ah*Bl
                mma_bf16(acc[mt][nt], ah[mt], bh0, bh1);  // Ah*Bh
            }
        }
        __syncthreads();
        if (it + 2 < T) load_tile(it + 2, it & 1);
    }

    // ---- C write ----
#pragma unroll
    for (int mt = 0; mt < 2; mt++) {
        int r = row0 + warp_m * 32 + mt * 16 + grp;
#pragma unroll
        for (int nt = 0; nt < 4; nt++) {
            int c = col0 + warp_n * 32 + nt * 8 + 2 * tig;
            float bx = 0.f, by = 0.f;
            if (hasb) { bx = bias1[c]; by = bias1[c + 1]; }
            if (r < Nr)
                *(float2*)&Cc[(size_t)r * HC + c] =
                    make_float2(acc[mt][nt][0] + bx, acc[mt][nt][1] + by);
            if (r + 8 < Nr)
                *(float2*)&Cc[(size_t)(r + 8) * HC + c] =
                    make_float2(acc[mt][nt][2] + bx, acc[mt][nt][3] + by);
        }
    }

    // ---- fused attention dots (feat branch only) ----
    if (blockIdx.z == 0) {
        const int head = blockIdx.x;
        float pes[2][2] = {{0.f, 0.f}, {0.f, 0.f}};
        float ped[2][2] = {{0.f, 0.f}, {0.f, 0.f}};
#pragma unroll
        for (int mt = 0; mt < 2; mt++)
#pragma unroll
            for (int nt = 0; nt < 4; nt++) {
                int cl = warp_n * 32 + nt * 8 + 2 * tig;
                float a0 = asrc[head * CH + cl], a1 = asrc[head * CH + cl + 1];
                float d0 = adst[head * CH + cl], d1 = adst[head * CH + cl + 1];
                pes[mt][0] += acc[mt][nt][0] * a0 + acc[mt][nt][1] * a1;
                pes[mt][1] += acc[mt][nt][2] * a0 + acc[mt][nt][3] * a1;
                ped[mt][0] += acc[mt][nt][0] * d0 + acc[mt][nt][1] * d1;
                ped[mt][1] += acc[mt][nt][2] * d0 + acc[mt][nt][3] * d1;
            }
#pragma unroll
        for (int o = 1; o <= 2; o <<= 1) {
#pragma unroll
            for (int mt = 0; mt < 2; mt++)
#pragma unroll
                for (int hh = 0; hh < 2; hh++) {
                    pes[mt][hh] += __shfl_xor_sync(0xffffffffu, pes[mt][hh], o);
                    ped[mt][hh] += __shfl_xor_sync(0xffffffffu, ped[mt][hh], o);
                }
        }
        if (tig == 0) {
#pragma unroll
            for (int mt = 0; mt < 2; mt++)
#pragma unroll
                for (int hh = 0; hh < 2; hh++) {
                    int lr = warp_m * 32 + mt * 16 + hh * 8 + grp;
                    atomicAdd(&sEs[lr], pes[mt][hh]);
                    atomicAdd(&sEd[lr], ped[mt][hh]);
                }
        }
        __syncthreads();
        if (tid < 128) {
            int node = row0 + tid;
            if (node < Nr) {
                es[node * NH + head] = sEs[tid];
                ed[node * NH + head] = sEd[tid];
            }
        }
    }
}

// ---------------- GAT softmax + aggregate: warp per (node, head) ----------------
__global__ __launch_bounds__(256) void agg_kernel(
    const float* __restrict__ feat, const float* __restrict__ es,
    const float* __restrict__ ed, const float* __restrict__ bias,
    const float* __restrict__ res, float* __restrict__ out)
{
    int gw = (blockIdx.x * blockDim.x + threadIdx.x) >> 5;
    int lane = threadIdx.x & 31;
    if (gw >= NN * NH) return;
    int node = gw >> 2, head = gw & 3;
    int s0 = g_rowptr[node], s1 = g_rowptr[node + 1];
    int ch = head * CH + 2 * lane;
    float accx = 0.f, accy = 0.f;

    if (s1 > s0) {
        float edv = ed[node * NH + head];
        // single-pass online softmax statistics (max + denominator)
        float m = -INFINITY, den = 0.f;
        for (int k = s0 + lane; k < s1; k += 32) {
            int s = g_srcsorted[k];
            float e = es[s * NH + head] + edv;
            e = (e >= 0.f) ? e : SLOPE * e;
            if (e > m) { den = den * __expf(m - e) + 1.f; m = e; }
            else den += __expf(e - m);
        }
#pragma unroll
        for (int o = 16; o; o >>= 1) {
            float mo  = __shfl_xor_sync(0xffffffffu, m, o);
            float dno = __shfl_xor_sync(0xffffffffu, den, o);
            float nm = fmaxf(m, mo);
            float f1 = (m == nm) ? 1.f : __expf(m - nm);
            float f2 = (mo == nm) ? 1.f : __expf(mo - nm);
            den = den * f1 + dno * f2;
            m = nm;
        }
        float inv = 1.f / (den + 1e-16f);
        // weighted gather (all lanes walk edges together; lanes = channels)
        for (int k = s0; k < s1; k++) {
            int s = g_srcsorted[k];
            float e = es[s * NH + head] + edv;
            e = (e >= 0.f) ? e : SLOPE * e;
            float w = __expf(e - m) * inv;
            float2 v = *(const float2*)&feat[(size_t)s * HC + ch];
            accx += w * v.x;
            accy += w * v.y;
        }
    }
    float2 bv = *(const float2*)&bias[ch];
    float2 rv = *(const float2*)&res[(size_t)node * HC + ch];
    float2 o2;
    o2.x = accx + bv.x + rv.x;
    o2.y = accy + bv.y + rv.y;
    *(float2*)&out[(size_t)node * HC + ch] = o2;
}

// ---------------- BatchNorm ----------------
__global__ __launch_bounds__(256) void bn_stats_kernel(const float* __restrict__ x) {
    int chn = threadIdx.x;
    int r0 = blockIdx.x * 64;
    int r1 = min(r0 + 64, NN);
    float s = 0.f, q = 0.f;
    for (int r = r0; r < r1; r++) {
        float v = x[(size_t)r * HC + chn];
        s += v; q += v * v;
    }
    atomicAdd(&g_bnacc[chn], s);
    atomicAdd(&g_bnacc[chn + HC], q);
}

__global__ void bn_finalize_kernel(const float* __restrict__ gma, const float* __restrict__ beta) {
    int c = threadIdx.x;
    float mean = g_bnacc[c] / (float)NN;
    float var  = g_bnacc[c + HC] / (float)NN - mean * mean;
    float a = gma[c] * rsqrtf(var + EPSBN);
    g_bnA[c] = a;
    g_bnB[c] = beta[c] - mean * a;
}

__global__ __launch_bounds__(256) void bn_apply_kernel(float* __restrict__ x) {
    int i = blockIdx.x * blockDim.x + threadIdx.x;
    if (i >= NN * HC / 4) return;
    float4 v = ((const float4*)x)[i];
    int c = (i * 4) & 255;
    v.x = fmaxf(v.x * g_bnA[c + 0] + g_bnB[c + 0], 0.f);
    v.y = fmaxf(v.y * g_bnA[c + 1] + g_bnB[c + 1], 0.f);
    v.z = fmaxf(v.z * g_bnA[c + 2] + g_bnB[c + 2], 0.f);
    v.w = fmaxf(v.w * g_bnA[c + 3] + g_bnB[c + 3], 0.f);
    ((float4*)x)[i] = v;
}

// ---------------- pooling (atomic-free; batch is sorted) ----------------
__global__ __launch_bounds__(256) void pool_kernel(const float* __restrict__ act,
                                                   const int* __restrict__ batch) {
    __shared__ int s_lo, s_hi;
    int g = blockIdx.x;
    int t = threadIdx.x;
    if (t == 0) {
        int lo = 0, hi = NN;
        while (lo < hi) { int mid = (lo + hi) >> 1; if (batch[mid] < g) lo = mid + 1; else hi = mid; }
        s_lo = lo;
        int lo2 = lo; hi = NN;
        while (lo2 < hi) { int mid = (lo2 + hi) >> 1; if (batch[mid] < g + 1) lo2 = mid + 1; else hi = mid; }
        s_hi = lo2;
    }
    __syncthreads();
    int lo = s_lo, hi = s_hi;
    float s = 0.f;
    for (int r = lo; r < hi; r++) s += act[(size_t)r * HC + t];
    float inv = (hi > lo) ? 1.0f / (float)(hi - lo) : 0.0f;
    g_pooled[(size_t)g * HC + t] = s * inv;
}

// ---------------- graph-level MLP ----------------
__global__ __launch_bounds__(128) void mlp_kernel(
    const float* __restrict__ fc1W, const float* __restrict__ fc1b,
    const float* __restrict__ fc2W, const float* __restrict__ fc2b,
    float* __restrict__ out)
{
    __shared__ float row[HC];
    __shared__ float red[128];
    int g = blockIdx.x, t = threadIdx.x;
    row[t]       = g_pooled[(size_t)g * HC + t];
    row[t + 128] = g_pooled[(size_t)g * HC + t + 128];
    __syncthreads();
    float a = fc1b[t];
#pragma unroll 8
    for (int k = 0; k < HC; k++) a += row[k] * fc1W[k * 128 + t];
    a = fmaxf(a, 0.f);
    for (int j = 0; j < 2; j++) {
        red[t] = a * fc2W[t * 2 + j];
        __syncthreads();
        for (int off = 64; off; off >>= 1) {
            if (t < off) red[t] += red[t + off];
            __syncthreads();
        }
        if (t == 0) out[g * 2 + j] = red[0] + fc2b[j];
        __syncthreads();
    }
}

// ---------------- host side ----------------
static void* symp(const void* sym) {
    void* p = nullptr;
    cudaGetSymbolAddress(&p, sym);
    return p;
}

extern "C" void kernel_launch(void* const* d_in, const int* in_sizes, int n_in,
                              void* d_out, int out_size)
{
    const float* x        = (const float*)d_in[0];
    const int*   edge_idx = (const int*)  d_in[1];
    const int*   batch    = (const int*)  d_in[3];
    const float* W1       = (const float*)d_in[4];
    const float* asrc1    = (const float*)d_in[5];
    const float* adst1    = (const float*)d_in[6];
    const float* b1       = (const float*)d_in[7];
    const float* res1W    = (const float*)d_in[8];
    const float* res1b    = (const float*)d_in[9];
    const float* bn1g     = (const float*)d_in[10];
    const float* bn1b     = (const float*)d_in[11];
    const float* W2       = (const float*)d_in[12];
    const float* asrc2    = (const float*)d_in[13];
    const float* adst2    = (const float*)d_in[14];
    const float* b2       = (const float*)d_in[15];
    const float* res2W    = (const float*)d_in[16];
    const float* res2b    = (const float*)d_in[17];
    const float* bn2g     = (const float*)d_in[18];
    const float* bn2b     = (const float*)d_in[19];
    const float* fc1W     = (const float*)d_in[20];
    const float* fc1b     = (const float*)d_in[21];
    const float* fc2W     = (const float*)d_in[22];
    const float* fc2b     = (const float*)d_in[23];
    float* out = (float*)d_out;

    float* feat  = (float*)symp(g_feat);
    float* res   = (float*)symp(g_res);
    float* act   = (float*)symp(g_act);
    float* es    = (float*)symp(g_es);
    float* ed    = (float*)symp(g_ed);
    int*   rowp  = (int*)  symp(g_rowptr);
    int*   curs  = (int*)  symp(g_cursor);
    int*   bsum  = (int*)  symp(g_blocksums);
    int*   boff  = (int*)  symp(g_blockoff);
    float* bnacc = (float*)symp(g_bnacc);
    float* bnA   = (float*)symp(g_bnA);
    float* bnB   = (float*)symp(g_bnB);

    const int NB = (NN + 255) / 256;
    const int EB = (EE + 255) / 256;
    const int WARPBLKS = (NN * NH * 32 + 255) / 256;
    dim3 gemm_grid(HC / 64, (NN + 127) / 128, 2);

    // launch order: gemm L1 placed at index 3 (ncu capture slot)
    zero_int_kernel<<<NB, 256>>>(curs, NN);                  // 0
    count_deg_kernel<<<EB, 256>>>(edge_idx);                 // 1
    scan_block_kernel<<<NB, 256>>>(curs, rowp, bsum, NN);    // 2

    gemm2tc_kernel<<<gemm_grid, 256>>>(x, W1, res1W, res1b, asrc1, adst1,
                                       nullptr, nullptr,
                                       feat, res, es, ed, NN, DIN);  // 3 <- profiled

    scan_block_kernel<<<1, 256>>>(bsum, boff, nullptr, NB);  // 4
    scan_add_kernel<<<NB, 256>>>(rowp, boff, NN);            // 5
    copy_int_kernel<<<NB, 256>>>(curs, rowp, NN);            // 6
    fill_csr_kernel<<<EB, 256>>>(edge_idx);                  // 7

    agg_kernel<<<WARPBLKS, 256>>>(feat, es, ed, b1, res, act);
    zero_float_kernel<<<2, 256>>>(bnacc, 2 * HC);
    bn_stats_kernel<<<(NN + 63) / 64, 256>>>(act);
    bn_finalize_kernel<<<1, HC>>>(bn1g, bn1b);
    // NOTE: no bn_apply here — BN1+ReLU fused into layer-2 GEMM A-load

    gemm2tc_kernel<<<gemm_grid, 256>>>(act, W2, res2W, res2b, asrc2, adst2,
                                       bnA, bnB,
                                       feat, res, es, ed, NN, HC);
    agg_kernel<<<WARPBLKS, 256>>>(feat, es, ed, b2, res, act);
    zero_float_kernel<<<2, 256>>>(bnacc, 2 * HC);
    bn_stats_kernel<<<(NN + 63) / 64, 256>>>(act);
    bn_finalize_kernel<<<1, HC>>>(bn2g, bn2b);
    bn_apply_kernel<<<(NN * HC / 4 + 255) / 256, 256>>>(act);

    pool_kernel<<<NG, 256>>>(act, batch);
    mlp_kernel<<<NG, 128>>>(fc1W, fc1b, fc2W, fc2b, out);
}